// round 3
// baseline (speedup 1.0000x reference)
#include <cuda_runtime.h>

#define HH 512
#define WW 512
#define CHN 6
#define BATCH 2
#define EPS_F 1e-6f

// reflect index into [0, n) (pad <= 4 so single reflection suffices)
__device__ __forceinline__ int refl(int i, int n) {
    if (i < 0) i = -i;
    if (i >= n) i = 2 * n - 2 - i;
    return i;
}

// upper-triangle (i<=j) linear index into 21-entry array
__device__ __forceinline__ constexpr int IU(int i, int j) {
    return i * 6 - i * (i - 1) / 2 + (j - i);
}
// lower-triangle (i>=j) linear index into 21-entry array
__device__ __forceinline__ constexpr int IL(int i, int j) {
    return i * (i + 1) / 2 + j;
}

// Per-pixel CCA from raw window sums.
// sxx/syy stored upper-tri (i<=j), sxy full row-major [i*6+j].
__device__ __forceinline__ float cca6(const float* sx, const float* sy,
                                      const float* sxx, const float* syy,
                                      const float* sxy, float inv_n) {
    float xm[6], ym[6];
#pragma unroll
    for (int i = 0; i < 6; i++) { xm[i] = sx[i] * inv_n; ym[i] = sy[i] * inv_n; }

    float cxx[21], cyy[21];
    {
        int t = 0;
#pragma unroll
        for (int i = 0; i < 6; i++)
#pragma unroll
            for (int j = i; j < 6; j++, t++) {
                cxx[t] = fmaf(-xm[i], xm[j], sxx[t] * inv_n);
                cyy[t] = fmaf(-ym[i], ym[j], syy[t] * inv_n);
            }
    }
#pragma unroll
    for (int i = 0; i < 6; i++) { cxx[IU(i, i)] += EPS_F; cyy[IU(i, i)] += EPS_F; }

    float cxy[36];
#pragma unroll
    for (int i = 0; i < 6; i++)
#pragma unroll
        for (int j = 0; j < 6; j++)
            cxy[i * 6 + j] = fmaf(-xm[i], ym[j], sxy[i * 6 + j] * inv_n);

    // Cholesky of cxx and cyy (lower L, 21 entries each)
    float Lx[21], Ly[21], ivx[6], ivy[6];
#pragma unroll
    for (int j = 0; j < 6; j++) {
        float dx = cxx[IU(j, j)], dy = cyy[IU(j, j)];
#pragma unroll
        for (int t = 0; t < j; t++) {
            dx = fmaf(-Lx[IL(j, t)], Lx[IL(j, t)], dx);
            dy = fmaf(-Ly[IL(j, t)], Ly[IL(j, t)], dy);
        }
        float sxr = sqrtf(dx), syr = sqrtf(dy);
        Lx[IL(j, j)] = sxr;
        Ly[IL(j, j)] = syr;
        ivx[j] = 1.0f / sxr;
        ivy[j] = 1.0f / syr;
#pragma unroll
        for (int i = j + 1; i < 6; i++) {
            float vx = cxx[IU(j, i)], vy = cyy[IU(j, i)];
#pragma unroll
            for (int t = 0; t < j; t++) {
                vx = fmaf(-Lx[IL(i, t)], Lx[IL(j, t)], vx);
                vy = fmaf(-Ly[IL(i, t)], Ly[IL(j, t)], vy);
            }
            Lx[IL(i, j)] = vx * ivx[j];
            Ly[IL(i, j)] = vy * ivy[j];
        }
    }

    // M = Lx^{-1} * cxy ; only upper triangle (i<=j) is needed downstream.
    float MN[21];
#pragma unroll
    for (int j = 0; j < 6; j++) {
#pragma unroll
        for (int i = 0; i <= j; i++) {
            float v = cxy[i * 6 + j];
#pragma unroll
            for (int t = 0; t < i; t++) v = fmaf(-Lx[IL(i, t)], MN[IU(t, j)], v);
            MN[IU(i, j)] = v * ivx[i];
        }
    }
    // N = M * Ly^{-1}, in place (solve N * Ly = M, back-substitution per row).
    float sim = 0.f;
#pragma unroll
    for (int i = 0; i < 6; i++) {
#pragma unroll
        for (int j = 5; j >= i; j--) {
            float v = MN[IU(i, j)];
#pragma unroll
            for (int t = j + 1; t < 6; t++) v = fmaf(-MN[IU(i, t)], Ly[IL(t, j)], v);
            v *= ivy[j];
            MN[IU(i, j)] = v;
            if (j == i) sim += fabsf(v);
        }
    }
    return sim * (1.0f / 6.0f);
}

// K = window size (2r+1), TILE = output tile side, NTX = column groups per row,
// RPP = TILE/NTX pixels per thread (sliding window along x).
template <int K, int TILE, int NTX>
__global__ __launch_bounds__(TILE* NTX) void cca_kernel(
    const float* __restrict__ x, const float* __restrict__ y,
    float* __restrict__ out, int ri) {
    constexpr int R = (K - 1) / 2;
    constexpr int PH = TILE + K - 1;
    constexpr int PW = TILE + K - 1;
    constexpr int PS = PW + 1;  // odd stride -> bank-conflict-free
    constexpr int RPP = TILE / NTX;
    constexpr float INV_N = 1.0f / (float)(K * K);

    extern __shared__ float sm[];  // [12][PH][PS]

    const int b = blockIdx.z;
    const int tx0 = blockIdx.x * TILE;
    const int ty0 = blockIdx.y * TILE;
    const int tid = threadIdx.x;

    // cooperative load of padded 12-channel tile
    for (int idx = tid; idx < 12 * PH * PW; idx += TILE * NTX) {
        int c = idx / (PH * PW);
        int rem = idx - c * (PH * PW);
        int row = rem / PW;
        int col = rem - row * PW;
        int gy = refl(ty0 - R + row, HH);
        int gx = refl(tx0 - R + col, WW);
        const float* src = (c < CHN) ? x : y;
        int cc = (c < CHN) ? c : c - CHN;
        sm[(c * PH + row) * PS + col] = src[((size_t)(b * CHN + cc) * HH + gy) * WW + gx];
    }
    __syncthreads();

    const int txg = tid & (NTX - 1);
    const int ty = tid / NTX;      // output row within tile
    const int c0 = txg * RPP;      // first output col within tile

    float sx[6], sy[6], sxx[21], syy[21], sxy[36];
#pragma unroll
    for (int i = 0; i < 6; i++) { sx[i] = 0.f; sy[i] = 0.f; }
#pragma unroll
    for (int i = 0; i < 21; i++) { sxx[i] = 0.f; syy[i] = 0.f; }
#pragma unroll
    for (int i = 0; i < 36; i++) sxy[i] = 0.f;

    auto loadvals = [&](int row, int col, float* xv, float* yv) {
#pragma unroll
        for (int c = 0; c < 6; c++) xv[c] = sm[(c * PH + row) * PS + col];
#pragma unroll
        for (int c = 0; c < 6; c++) yv[c] = sm[((c + 6) * PH + row) * PS + col];
    };
    auto accumAdd = [&](int row, int col) {
        float xv[6], yv[6];
        loadvals(row, col, xv, yv);
#pragma unroll
        for (int i = 0; i < 6; i++) { sx[i] += xv[i]; sy[i] += yv[i]; }
        int t = 0;
#pragma unroll
        for (int i = 0; i < 6; i++)
#pragma unroll
            for (int j = i; j < 6; j++, t++) {
                sxx[t] = fmaf(xv[i], xv[j], sxx[t]);
                syy[t] = fmaf(yv[i], yv[j], syy[t]);
            }
#pragma unroll
        for (int i = 0; i < 6; i++)
#pragma unroll
            for (int j = 0; j < 6; j++)
                sxy[i * 6 + j] = fmaf(xv[i], yv[j], sxy[i * 6 + j]);
    };
    auto accumSub = [&](int row, int col) {
        float xv[6], yv[6];
        loadvals(row, col, xv, yv);
#pragma unroll
        for (int i = 0; i < 6; i++) { sx[i] -= xv[i]; sy[i] -= yv[i]; }
        int t = 0;
#pragma unroll
        for (int i = 0; i < 6; i++)
#pragma unroll
            for (int j = i; j < 6; j++, t++) {
                sxx[t] = fmaf(-xv[i], xv[j], sxx[t]);
                syy[t] = fmaf(-yv[i], yv[j], syy[t]);
            }
#pragma unroll
        for (int i = 0; i < 6; i++)
#pragma unroll
            for (int j = 0; j < 6; j++)
                sxy[i * 6 + j] = fmaf(-xv[i], yv[j], sxy[i * 6 + j]);
    };

    // initial full window for first pixel
#pragma unroll 1
    for (int r = 0; r < K; ++r)
#pragma unroll 1
        for (int c = 0; c < K; ++c) accumAdd(ty + r, c0 + c);

    const int gy = ty0 + ty;
    {
        float sim = cca6(sx, sy, sxx, syy, sxy, INV_N);
        out[(((size_t)b * HH + gy) * WW + (tx0 + c0)) * 2 + ri] = sim;
    }

#pragma unroll 1
    for (int p = 1; p < RPP; ++p) {
#pragma unroll 1
        for (int r = 0; r < K; ++r) {
            accumSub(ty + r, c0 + p - 1);
            accumAdd(ty + r, c0 + p - 1 + K);
        }
        float sim = cca6(sx, sy, sxx, syy, sxy, INV_N);
        out[(((size_t)b * HH + gy) * WW + (tx0 + c0 + p)) * 2 + ri] = sim;
    }
}

extern "C" void kernel_launch(void* const* d_in, const int* in_sizes, int n_in,
                              void* d_out, int out_size) {
    (void)in_sizes; (void)n_in; (void)out_size;
    const float* x = (const float*)d_in[0];
    const float* y = (const float*)d_in[1];
    float* out = (float*)d_out;

    constexpr int TILE = 32, NTX = 4;
    dim3 grid(WW / TILE, HH / TILE, BATCH);
    dim3 block(TILE * NTX);

    // r=2 -> K=5, padded 36x(36+1)
    constexpr int SM5 = 12 * 36 * 37 * 4;
    // r=4 -> K=9, padded 40x(40+1)
    constexpr int SM9 = 12 * 40 * 41 * 4;

    cudaFuncSetAttribute(cca_kernel<5, TILE, NTX>,
                         cudaFuncAttributeMaxDynamicSharedMemorySize, SM5);
    cudaFuncSetAttribute(cca_kernel<9, TILE, NTX>,
                         cudaFuncAttributeMaxDynamicSharedMemorySize, SM9);

    cca_kernel<5, TILE, NTX><<<grid, block, SM5>>>(x, y, out, 0);
    cca_kernel<9, TILE, NTX><<<grid, block, SM9>>>(x, y, out, 1);
}

// round 4
// speedup vs baseline: 1.1576x; 1.1576x over previous
#include <cuda_runtime.h>

#define HH 512
#define WW 512
#define CHN 6
#define BATCH 2
#define EPS_F 1e-6f

__device__ __forceinline__ int refl(int i, int n) {
    if (i < 0) i = -i;
    if (i >= n) i = 2 * n - 2 - i;
    return i;
}

// upper-triangle (i<=j) linear index into 21-entry array
__device__ __forceinline__ constexpr int IU(int i, int j) {
    return i * 6 - i * (i - 1) / 2 + (j - i);
}
// lower-triangle (i>=j) linear index into 21-entry array
__device__ __forceinline__ constexpr int IL(int i, int j) {
    return i * (i + 1) / 2 + j;
}

// Per-pixel CCA from raw window sums.
// sxx/syy stored upper-tri (i<=j), sxy full row-major [i*6+j].
__device__ __forceinline__ float cca6(const float* sx, const float* sy,
                                      const float* sxx, const float* syy,
                                      const float* sxy, float inv_n) {
    float xm[6], ym[6];
#pragma unroll
    for (int i = 0; i < 6; i++) { xm[i] = sx[i] * inv_n; ym[i] = sy[i] * inv_n; }

    float cxx[21], cyy[21];
    {
        int t = 0;
#pragma unroll
        for (int i = 0; i < 6; i++)
#pragma unroll
            for (int j = i; j < 6; j++, t++) {
                cxx[t] = fmaf(-xm[i], xm[j], sxx[t] * inv_n);
                cyy[t] = fmaf(-ym[i], ym[j], syy[t] * inv_n);
            }
    }
#pragma unroll
    for (int i = 0; i < 6; i++) { cxx[IU(i, i)] += EPS_F; cyy[IU(i, i)] += EPS_F; }

    float cxy[36];
#pragma unroll
    for (int i = 0; i < 6; i++)
#pragma unroll
        for (int j = 0; j < 6; j++)
            cxy[i * 6 + j] = fmaf(-xm[i], ym[j], sxy[i * 6 + j] * inv_n);

    // Cholesky of cxx and cyy (lower L, 21 entries each); rsqrt-based:
    // iv = rsqrt(d), L_jj = d * iv  (avoids full-precision div + sqrt)
    float Lx[21], Ly[21], ivx[6], ivy[6];
#pragma unroll
    for (int j = 0; j < 6; j++) {
        float dx = cxx[IU(j, j)], dy = cyy[IU(j, j)];
#pragma unroll
        for (int t = 0; t < j; t++) {
            dx = fmaf(-Lx[IL(j, t)], Lx[IL(j, t)], dx);
            dy = fmaf(-Ly[IL(j, t)], Ly[IL(j, t)], dy);
        }
        float rx = rsqrtf(dx), ry = rsqrtf(dy);
        ivx[j] = rx;
        ivy[j] = ry;
        Lx[IL(j, j)] = dx * rx;
        Ly[IL(j, j)] = dy * ry;
#pragma unroll
        for (int i = j + 1; i < 6; i++) {
            float vx = cxx[IU(j, i)], vy = cyy[IU(j, i)];
#pragma unroll
            for (int t = 0; t < j; t++) {
                vx = fmaf(-Lx[IL(i, t)], Lx[IL(j, t)], vx);
                vy = fmaf(-Ly[IL(i, t)], Ly[IL(j, t)], vy);
            }
            Lx[IL(i, j)] = vx * ivx[j];
            Ly[IL(i, j)] = vy * ivy[j];
        }
    }

    // M = Lx^{-1} * cxy ; only upper triangle (i<=j) is needed downstream.
    float MN[21];
#pragma unroll
    for (int j = 0; j < 6; j++) {
#pragma unroll
        for (int i = 0; i <= j; i++) {
            float v = cxy[i * 6 + j];
#pragma unroll
            for (int t = 0; t < i; t++) v = fmaf(-Lx[IL(i, t)], MN[IU(t, j)], v);
            MN[IU(i, j)] = v * ivx[i];
        }
    }
    // N = M * Ly^{-1}, in place (solve N * Ly = M, back-substitution per row).
    float sim = 0.f;
#pragma unroll
    for (int i = 0; i < 6; i++) {
#pragma unroll
        for (int j = 5; j >= i; j--) {
            float v = MN[IU(i, j)];
#pragma unroll
            for (int t = j + 1; t < 6; t++) v = fmaf(-MN[IU(i, t)], Ly[IL(t, j)], v);
            v *= ivy[j];
            MN[IU(i, j)] = v;
            if (j == i) sim += fabsf(v);
        }
    }
    return sim * (1.0f / 6.0f);
}

// K = window size (2r+1), TILE = output tile side, NTX = column groups per row,
// RPP = TILE/NTX pixels per thread (sliding window along x).
// Shared tile packs (x_c, y_c) as float2 per channel plane -> 6 LDS.64/point.
template <int K, int TILE, int NTX>
__global__ __launch_bounds__(TILE* NTX) void cca_kernel(
    const float* __restrict__ x, const float* __restrict__ y,
    float* __restrict__ out, int ri) {
    constexpr int R = (K - 1) / 2;
    constexpr int PH = TILE + K - 1;
    constexpr int PW = TILE + K - 1;
    constexpr int PS = PW + 1;  // odd stride
    constexpr int RPP = TILE / NTX;
    constexpr float INV_N = 1.0f / (float)(K * K);

    extern __shared__ float2 sm[];  // [6][PH][PS] of (x,y)

    const int b = blockIdx.z;
    const int tx0 = blockIdx.x * TILE;
    const int ty0 = blockIdx.y * TILE;
    const int tid = threadIdx.x;

    // cooperative load of padded 6-channel (x,y)-packed tile
    for (int idx = tid; idx < 6 * PH * PW; idx += TILE * NTX) {
        int c = idx / (PH * PW);
        int rem = idx - c * (PH * PW);
        int row = rem / PW;
        int col = rem - row * PW;
        int gy = refl(ty0 - R + row, HH);
        int gx = refl(tx0 - R + col, WW);
        size_t gidx = ((size_t)(b * CHN + c) * HH + gy) * WW + gx;
        float2 v;
        v.x = x[gidx];
        v.y = y[gidx];
        sm[(c * PH + row) * PS + col] = v;
    }
    __syncthreads();

    const int txg = tid & (NTX - 1);
    const int ty = tid / NTX;      // output row within tile
    const int c0 = txg * RPP;      // first output col within tile

    float sx[6], sy[6], sxx[21], syy[21], sxy[36];
#pragma unroll
    for (int i = 0; i < 6; i++) { sx[i] = 0.f; sy[i] = 0.f; }
#pragma unroll
    for (int i = 0; i < 21; i++) { sxx[i] = 0.f; syy[i] = 0.f; }
#pragma unroll
    for (int i = 0; i < 36; i++) sxy[i] = 0.f;

    auto loadvals = [&](int row, int col, float* xv, float* yv) {
#pragma unroll
        for (int c = 0; c < 6; c++) {
            float2 v = sm[(c * PH + row) * PS + col];
            xv[c] = v.x;
            yv[c] = v.y;
        }
    };
    auto accumAdd = [&](int row, int col) {
        float xv[6], yv[6];
        loadvals(row, col, xv, yv);
#pragma unroll
        for (int i = 0; i < 6; i++) { sx[i] += xv[i]; sy[i] += yv[i]; }
        int t = 0;
#pragma unroll
        for (int i = 0; i < 6; i++)
#pragma unroll
            for (int j = i; j < 6; j++, t++) {
                sxx[t] = fmaf(xv[i], xv[j], sxx[t]);
                syy[t] = fmaf(yv[i], yv[j], syy[t]);
            }
#pragma unroll
        for (int i = 0; i < 6; i++)
#pragma unroll
            for (int j = 0; j < 6; j++)
                sxy[i * 6 + j] = fmaf(xv[i], yv[j], sxy[i * 6 + j]);
    };
    auto accumSub = [&](int row, int col) {
        float xv[6], yv[6];
        loadvals(row, col, xv, yv);
#pragma unroll
        for (int i = 0; i < 6; i++) { sx[i] -= xv[i]; sy[i] -= yv[i]; }
        int t = 0;
#pragma unroll
        for (int i = 0; i < 6; i++)
#pragma unroll
            for (int j = i; j < 6; j++, t++) {
                sxx[t] = fmaf(-xv[i], xv[j], sxx[t]);
                syy[t] = fmaf(-yv[i], yv[j], syy[t]);
            }
#pragma unroll
        for (int i = 0; i < 6; i++)
#pragma unroll
            for (int j = 0; j < 6; j++)
                sxy[i * 6 + j] = fmaf(-xv[i], yv[j], sxy[i * 6 + j]);
    };

    // initial full window for first pixel
#pragma unroll 1
    for (int r = 0; r < K; ++r)
#pragma unroll 1
        for (int c = 0; c < K; ++c) accumAdd(ty + r, c0 + c);

    const int gy = ty0 + ty;
    {
        float sim = cca6(sx, sy, sxx, syy, sxy, INV_N);
        out[(((size_t)b * HH + gy) * WW + (tx0 + c0)) * 2 + ri] = sim;
    }

#pragma unroll 1
    for (int p = 1; p < RPP; ++p) {
#pragma unroll 1
        for (int r = 0; r < K; ++r) {
            accumSub(ty + r, c0 + p - 1);
            accumAdd(ty + r, c0 + p - 1 + K);
        }
        float sim = cca6(sx, sy, sxx, syy, sxy, INV_N);
        out[(((size_t)b * HH + gy) * WW + (tx0 + c0 + p)) * 2 + ri] = sim;
    }
}

extern "C" void kernel_launch(void* const* d_in, const int* in_sizes, int n_in,
                              void* d_out, int out_size) {
    (void)in_sizes; (void)n_in; (void)out_size;
    const float* x = (const float*)d_in[0];
    const float* y = (const float*)d_in[1];
    float* out = (float*)d_out;

    constexpr int TILE = 32, NTX = 8;
    dim3 grid(WW / TILE, HH / TILE, BATCH);
    dim3 block(TILE * NTX);

    // r=2 -> K=5: 6 planes of 36x37 float2
    constexpr int SM5 = 6 * 36 * 37 * 8;
    // r=4 -> K=9: 6 planes of 40x41 float2
    constexpr int SM9 = 6 * 40 * 41 * 8;

    cudaFuncSetAttribute(cca_kernel<5, TILE, NTX>,
                         cudaFuncAttributeMaxDynamicSharedMemorySize, SM5);
    cudaFuncSetAttribute(cca_kernel<9, TILE, NTX>,
                         cudaFuncAttributeMaxDynamicSharedMemorySize, SM9);

    cca_kernel<5, TILE, NTX><<<grid, block, SM5>>>(x, y, out, 0);
    cca_kernel<9, TILE, NTX><<<grid, block, SM9>>>(x, y, out, 1);
}

// round 5
// speedup vs baseline: 1.4482x; 1.2511x over previous
#include <cuda_runtime.h>

#define HH 512
#define WW 512
#define CHN 6
#define BATCH 2
#define EPS_F 1e-6f

__device__ __forceinline__ int refl(int i, int n) {
    if (i < 0) i = -i;
    if (i >= n) i = 2 * n - 2 - i;
    return i;
}

// upper-triangle (i<=j) linear index into 21-entry array
__device__ __forceinline__ constexpr int IU(int i, int j) {
    return i * 6 - i * (i - 1) / 2 + (j - i);
}
// lower-triangle (i>=j) linear index into 21-entry array
__device__ __forceinline__ constexpr int IL(int i, int j) {
    return i * (i + 1) / 2 + j;
}

// Per-pixel CCA directly from raw window sums. Covariance entries are
// materialized inline at their single use (no cxx/cyy/cxy register arrays).
// sxx/syy upper-tri (i<=j), sxy full row-major [i*6+j].
__device__ __forceinline__ float cca6(const float* sx, const float* sy,
                                      const float* sxx, const float* syy,
                                      const float* sxy, float inv_n) {
    float xm[6], ym[6];
#pragma unroll
    for (int i = 0; i < 6; i++) { xm[i] = sx[i] * inv_n; ym[i] = sy[i] * inv_n; }

    // Cholesky of cxx and cyy (lower L, 21 entries each); rsqrt-based.
    float Lx[21], Ly[21], ivx[6], ivy[6];
#pragma unroll
    for (int j = 0; j < 6; j++) {
        float dx = fmaf(-xm[j], xm[j], sxx[IU(j, j)] * inv_n) + EPS_F;
        float dy = fmaf(-ym[j], ym[j], syy[IU(j, j)] * inv_n) + EPS_F;
#pragma unroll
        for (int t = 0; t < j; t++) {
            dx = fmaf(-Lx[IL(j, t)], Lx[IL(j, t)], dx);
            dy = fmaf(-Ly[IL(j, t)], Ly[IL(j, t)], dy);
        }
        float rx = rsqrtf(dx), ry = rsqrtf(dy);
        ivx[j] = rx;
        ivy[j] = ry;
        Lx[IL(j, j)] = dx * rx;
        Ly[IL(j, j)] = dy * ry;
#pragma unroll
        for (int i = j + 1; i < 6; i++) {
            float vx = fmaf(-xm[j], xm[i], sxx[IU(j, i)] * inv_n);
            float vy = fmaf(-ym[j], ym[i], syy[IU(j, i)] * inv_n);
#pragma unroll
            for (int t = 0; t < j; t++) {
                vx = fmaf(-Lx[IL(i, t)], Lx[IL(j, t)], vx);
                vy = fmaf(-Ly[IL(i, t)], Ly[IL(j, t)], vy);
            }
            Lx[IL(i, j)] = vx * ivx[j];
            Ly[IL(i, j)] = vy * ivy[j];
        }
    }

    // M = Lx^{-1} * cxy ; only upper triangle (i<=j) needed downstream.
    // cxy(i,j) materialized inline from sxy.
    float MN[21];
#pragma unroll
    for (int j = 0; j < 6; j++) {
#pragma unroll
        for (int i = 0; i <= j; i++) {
            float v = fmaf(-xm[i], ym[j], sxy[i * 6 + j] * inv_n);
#pragma unroll
            for (int t = 0; t < i; t++) v = fmaf(-Lx[IL(i, t)], MN[IU(t, j)], v);
            MN[IU(i, j)] = v * ivx[i];
        }
    }
    // N = M * Ly^{-1}, in place (solve N * Ly = M, back-substitution per row).
    float sim = 0.f;
#pragma unroll
    for (int i = 0; i < 6; i++) {
#pragma unroll
        for (int j = 5; j >= i; j--) {
            float v = MN[IU(i, j)];
#pragma unroll
            for (int t = j + 1; t < 6; t++) v = fmaf(-MN[IU(i, t)], Ly[IL(t, j)], v);
            v *= ivy[j];
            MN[IU(i, j)] = v;
            if (j == i) sim += fabsf(v);
        }
    }
    return sim * (1.0f / 6.0f);
}

// K = window size (2r+1), TILE = output tile side, NTX = column groups per row,
// RPP = TILE/NTX pixels per thread (sliding window along x).
// Shared tile packs (x_c, y_c) as float2 per channel plane -> 6 LDS.64/point.
template <int K, int TILE, int NTX>
__global__ __launch_bounds__(TILE* NTX, 2) void cca_kernel(
    const float* __restrict__ x, const float* __restrict__ y,
    float* __restrict__ out, int ri) {
    constexpr int R = (K - 1) / 2;
    constexpr int PH = TILE + K - 1;
    constexpr int PW = TILE + K - 1;
    constexpr int PS = PW + 1;  // odd stride
    constexpr int RPP = TILE / NTX;
    constexpr float INV_N = 1.0f / (float)(K * K);

    extern __shared__ float2 sm[];  // [6][PH][PS] of (x,y)

    const int b = blockIdx.z;
    const int tx0 = blockIdx.x * TILE;
    const int ty0 = blockIdx.y * TILE;
    const int tid = threadIdx.x;

    // cooperative load of padded 6-channel (x,y)-packed tile
    for (int idx = tid; idx < 6 * PH * PW; idx += TILE * NTX) {
        int c = idx / (PH * PW);
        int rem = idx - c * (PH * PW);
        int row = rem / PW;
        int col = rem - row * PW;
        int gy = refl(ty0 - R + row, HH);
        int gx = refl(tx0 - R + col, WW);
        size_t gidx = ((size_t)(b * CHN + c) * HH + gy) * WW + gx;
        float2 v;
        v.x = x[gidx];
        v.y = y[gidx];
        sm[(c * PH + row) * PS + col] = v;
    }
    __syncthreads();

    const int txg = tid & (NTX - 1);
    const int ty = tid / NTX;      // output row within tile
    const int c0 = txg * RPP;      // first output col within tile

    float sx[6], sy[6], sxx[21], syy[21], sxy[36];
#pragma unroll
    for (int i = 0; i < 6; i++) { sx[i] = 0.f; sy[i] = 0.f; }
#pragma unroll
    for (int i = 0; i < 21; i++) { sxx[i] = 0.f; syy[i] = 0.f; }
#pragma unroll
    for (int i = 0; i < 36; i++) sxy[i] = 0.f;

    auto loadvals = [&](int row, int col, float* xv, float* yv) {
#pragma unroll
        for (int c = 0; c < 6; c++) {
            float2 v = sm[(c * PH + row) * PS + col];
            xv[c] = v.x;
            yv[c] = v.y;
        }
    };
    auto accumAdd = [&](int row, int col) {
        float xv[6], yv[6];
        loadvals(row, col, xv, yv);
#pragma unroll
        for (int i = 0; i < 6; i++) { sx[i] += xv[i]; sy[i] += yv[i]; }
        int t = 0;
#pragma unroll
        for (int i = 0; i < 6; i++)
#pragma unroll
            for (int j = i; j < 6; j++, t++) {
                sxx[t] = fmaf(xv[i], xv[j], sxx[t]);
                syy[t] = fmaf(yv[i], yv[j], syy[t]);
            }
#pragma unroll
        for (int i = 0; i < 6; i++)
#pragma unroll
            for (int j = 0; j < 6; j++)
                sxy[i * 6 + j] = fmaf(xv[i], yv[j], sxy[i * 6 + j]);
    };
    auto accumSub = [&](int row, int col) {
        float xv[6], yv[6];
        loadvals(row, col, xv, yv);
#pragma unroll
        for (int i = 0; i < 6; i++) { sx[i] -= xv[i]; sy[i] -= yv[i]; }
        int t = 0;
#pragma unroll
        for (int i = 0; i < 6; i++)
#pragma unroll
            for (int j = i; j < 6; j++, t++) {
                sxx[t] = fmaf(-xv[i], xv[j], sxx[t]);
                syy[t] = fmaf(-yv[i], yv[j], syy[t]);
            }
#pragma unroll
        for (int i = 0; i < 6; i++)
#pragma unroll
            for (int j = 0; j < 6; j++)
                sxy[i * 6 + j] = fmaf(-xv[i], yv[j], sxy[i * 6 + j]);
    };

    // initial full window for first pixel
#pragma unroll 1
    for (int r = 0; r < K; ++r)
#pragma unroll 1
        for (int c = 0; c < K; ++c) accumAdd(ty + r, c0 + c);

    const int gy = ty0 + ty;
    {
        float sim = cca6(sx, sy, sxx, syy, sxy, INV_N);
        out[(((size_t)b * HH + gy) * WW + (tx0 + c0)) * 2 + ri] = sim;
    }

#pragma unroll 1
    for (int p = 1; p < RPP; ++p) {
#pragma unroll 1
        for (int r = 0; r < K; ++r) {
            accumSub(ty + r, c0 + p - 1);
            accumAdd(ty + r, c0 + p - 1 + K);
        }
        float sim = cca6(sx, sy, sxx, syy, sxy, INV_N);
        out[(((size_t)b * HH + gy) * WW + (tx0 + c0 + p)) * 2 + ri] = sim;
    }
}

extern "C" void kernel_launch(void* const* d_in, const int* in_sizes, int n_in,
                              void* d_out, int out_size) {
    (void)in_sizes; (void)n_in; (void)out_size;
    const float* x = (const float*)d_in[0];
    const float* y = (const float*)d_in[1];
    float* out = (float*)d_out;

    constexpr int TILE = 32, NTX = 8;
    dim3 grid(WW / TILE, HH / TILE, BATCH);
    dim3 block(TILE * NTX);

    // r=2 -> K=5: 6 planes of 36x37 float2
    constexpr int SM5 = 6 * 36 * 37 * 8;
    // r=4 -> K=9: 6 planes of 40x41 float2
    constexpr int SM9 = 6 * 40 * 41 * 8;

    cudaFuncSetAttribute(cca_kernel<5, TILE, NTX>,
                         cudaFuncAttributeMaxDynamicSharedMemorySize, SM5);
    cudaFuncSetAttribute(cca_kernel<9, TILE, NTX>,
                         cudaFuncAttributeMaxDynamicSharedMemorySize, SM9);

    cca_kernel<5, TILE, NTX><<<grid, block, SM5>>>(x, y, out, 0);
    cca_kernel<9, TILE, NTX><<<grid, block, SM9>>>(x, y, out, 1);
}